// round 1
// baseline (speedup 1.0000x reference)
#include <cuda_runtime.h>
#include <math.h>

// Problem constants
#define WSZ   8
#define SSZ   4
#define HEADS 4
#define DHD   32
#define CDIM  128
#define T3IN  384        // 3 * heads * dh
#define LTOK  64         // tokens per window
#define HDIM  256
#define NSIDE 32         // windows per side
#define BATCH 8
#define NWIN  (BATCH * NSIDE * NSIDE)   // 8192
#define SCALE 0.1767766952966369f       // 32^-0.5

// SMEM layout (floats)
#define XS_STRIDE 132
#define XS_OFF    0
#define XS_SIZE   (64 * XS_STRIDE)          // 8448
#define WB_OFF    XS_SIZE                    // wbuf [32][384]
#define WB_SIZE   (32 * 384)                 // 12288
#define QK_STRIDE 386
#define QK_OFF    (WB_OFF + WB_SIZE)         // 20736
#define QK_SIZE   (64 * QK_STRIDE)           // 24704
#define SMEM_FLOATS (QK_OFF + QK_SIZE)       // 45440
#define SMEM_BYTES  (SMEM_FLOATS * 4)        // 181760

#define PO_STRIDE 130                        // proj-out reuses QK region

// ---- packed f32x2 helpers (FFMA2: 2 fp32 MACs per instruction) ----
__device__ __forceinline__ unsigned long long pk2(float x, float y) {
    unsigned long long r;
    asm("mov.b64 %0, {%1,%2};" : "=l"(r) : "f"(x), "f"(y));
    return r;
}
__device__ __forceinline__ void upk2(unsigned long long v, float& x, float& y) {
    asm("mov.b64 {%0,%1}, %2;" : "=f"(x), "=f"(y) : "l"(v));
}
__device__ __forceinline__ unsigned long long ffma2(unsigned long long a,
                                                    unsigned long long b,
                                                    unsigned long long c) {
    unsigned long long d;
    asm("fma.rn.f32x2 %0, %1, %2, %3;" : "=l"(d) : "l"(a), "l"(b), "l"(c));
    return d;
}

__global__ __launch_bounds__(256, 1)
void swin_attn_kernel(const float* __restrict__ x,
                      const float* __restrict__ wqkv,
                      const float* __restrict__ wproj,
                      const float* __restrict__ bproj,
                      float* __restrict__ out) {
    extern __shared__ float sm[];
    float* xs   = sm + XS_OFF;   // [64][132]: input tile, later attn-out tile
    float* wbuf = sm + WB_OFF;   // [32][384] weight chunk
    float* qk   = sm + QK_OFF;   // [64][386] qkv, later [64][130] proj-out

    const int tid = threadIdx.x;
    const int win = blockIdx.x;
    const int b   = win >> 10;
    const int wh  = (win >> 5) & 31;
    const int ww  = win & 31;

    // ---------------- Phase 1: gather (cyclic shift + window partition) ----
    {
        const int l  = tid & 63;           // fixed per thread (256 % 64 == 0)
        const int r  = l >> 3, c = l & 7;
        const int h  = (wh * 8 + r + SSZ) & 255;
        const int w  = (ww * 8 + c + SSZ) & 255;
        const int ch0 = tid >> 6;          // 0..3
        const long base = ((long)b * CDIM * HDIM + (long)h) * 256 + w;
        #pragma unroll
        for (int it = 0; it < 32; ++it) {
            int ch = ch0 + it * 4;
            xs[l * XS_STRIDE + ch] = x[base + (long)ch * (HDIM * 256)];
        }
    }
    __syncthreads();

    const int ty = tid >> 5;   // 0..7  (row group)
    const int tx = tid & 31;   // 0..31 (col-pair lane)

    // ---------------- Phase 2: QKV GEMM  [64,128]@[128,384] -----------------
    unsigned long long acc[8][6];
    #pragma unroll
    for (int i = 0; i < 8; ++i)
        #pragma unroll
        for (int jj = 0; jj < 6; ++jj) acc[i][jj] = 0ull;

    for (int cc = 0; cc < 4; ++cc) {
        #pragma unroll
        for (int it = 0; it < 48; ++it) {
            int idx = tid + it * 256;
            wbuf[idx] = wqkv[cc * 32 * T3IN + idx];
        }
        __syncthreads();
        #pragma unroll 4
        for (int chl = 0; chl < 32; ++chl) {
            unsigned long long a2[8];
            #pragma unroll
            for (int i = 0; i < 8; ++i) {
                float a = xs[(ty * 8 + i) * XS_STRIDE + cc * 32 + chl];
                a2[i] = pk2(a, a);
            }
            #pragma unroll
            for (int jj = 0; jj < 6; ++jj) {
                unsigned long long b2 =
                    *(const unsigned long long*)&wbuf[chl * T3IN + jj * 64 + tx * 2];
                #pragma unroll
                for (int i = 0; i < 8; ++i) acc[i][jj] = ffma2(a2[i], b2, acc[i][jj]);
            }
        }
        __syncthreads();
    }
    #pragma unroll
    for (int i = 0; i < 8; ++i)
        #pragma unroll
        for (int jj = 0; jj < 6; ++jj)
            *(unsigned long long*)&qk[(ty * 8 + i) * QK_STRIDE + jj * 64 + tx * 2] =
                acc[i][jj];
    __syncthreads();

    // ---------------- Phase 3: attention (per head, per query row) ----------
    {
        const int hh = tid >> 6;   // head 0..3
        const int l  = tid & 63;   // query row

        // q row, pre-scaled
        unsigned long long q2[16];
        const float* qrow = &qk[l * QK_STRIDE + hh * DHD];
        #pragma unroll
        for (int d2 = 0; d2 < 16; ++d2) {
            unsigned long long v = *(const unsigned long long*)&qrow[2 * d2];
            float qx, qy; upk2(v, qx, qy);
            q2[d2] = pk2(qx * SCALE, qy * SCALE);
        }

        // S = q . k^T
        float s[64];
        #pragma unroll
        for (int m = 0; m < 64; ++m) {
            const float* krow = &qk[m * QK_STRIDE + CDIM + hh * DHD];
            unsigned long long a2 = 0ull;
            #pragma unroll
            for (int d2 = 0; d2 < 16; ++d2)
                a2 = ffma2(q2[d2],
                           *(const unsigned long long*)&krow[2 * d2], a2);
            float ax, ay; upk2(a2, ax, ay);
            s[m] = ax + ay;
        }

        // softmax (row in registers)
        float mx = -1e30f;
        #pragma unroll
        for (int m = 0; m < 64; ++m) mx = fmaxf(mx, s[m]);
        float sum = 0.f;
        #pragma unroll
        for (int m = 0; m < 64; ++m) { float e = __expf(s[m] - mx); s[m] = e; sum += e; }
        const float inv = 1.0f / sum;

        // O = P @ V   (normalize at the end)
        unsigned long long o2[16];
        #pragma unroll
        for (int d2 = 0; d2 < 16; ++d2) o2[d2] = 0ull;
        #pragma unroll
        for (int m = 0; m < 64; ++m) {
            unsigned long long p2 = pk2(s[m], s[m]);
            const float* vrow = &qk[m * QK_STRIDE + 2 * CDIM + hh * DHD];
            #pragma unroll
            for (int d2 = 0; d2 < 16; ++d2)
                o2[d2] = ffma2(p2,
                               *(const unsigned long long*)&vrow[2 * d2], o2[d2]);
        }
        #pragma unroll
        for (int d2 = 0; d2 < 16; ++d2) {
            float ox, oy; upk2(o2[d2], ox, oy);
            float2 v; v.x = ox * inv; v.y = oy * inv;
            *(float2*)&xs[l * XS_STRIDE + hh * DHD + 2 * d2] = v;
        }
    }
    __syncthreads();

    // ---------------- Phase 4: proj GEMM [64,128]@[128,128] + bias ----------
    unsigned long long pa[8][2];
    #pragma unroll
    for (int i = 0; i < 8; ++i) { pa[i][0] = 0ull; pa[i][1] = 0ull; }

    for (int cc = 0; cc < 4; ++cc) {
        #pragma unroll
        for (int it = 0; it < 16; ++it) {
            int idx = tid + it * 256;
            wbuf[idx] = wproj[cc * 32 * CDIM + idx];
        }
        __syncthreads();
        #pragma unroll 4
        for (int chl = 0; chl < 32; ++chl) {
            unsigned long long a2[8];
            #pragma unroll
            for (int i = 0; i < 8; ++i) {
                float a = xs[(ty * 8 + i) * XS_STRIDE + cc * 32 + chl];
                a2[i] = pk2(a, a);
            }
            #pragma unroll
            for (int jj = 0; jj < 2; ++jj) {
                unsigned long long b2 =
                    *(const unsigned long long*)&wbuf[chl * CDIM + jj * 64 + tx * 2];
                #pragma unroll
                for (int i = 0; i < 8; ++i) pa[i][jj] = ffma2(a2[i], b2, pa[i][jj]);
            }
        }
        __syncthreads();
    }
    #pragma unroll
    for (int jj = 0; jj < 2; ++jj) {
        const int j = jj * 64 + tx * 2;
        const float bx = bproj[j], by = bproj[j + 1];
        #pragma unroll
        for (int i = 0; i < 8; ++i) {
            float ox, oy; upk2(pa[i][jj], ox, oy);
            float2 v; v.x = ox + bx; v.y = oy + by;
            *(float2*)&qk[(ty * 8 + i) * PO_STRIDE + j] = v;
        }
    }
    __syncthreads();

    // ---------------- Phase 5: scatter (window reverse + inverse shift) -----
    {
        const int l  = tid & 63;
        const int r  = l >> 3, c = l & 7;
        const int h  = (wh * 8 + r + SSZ) & 255;
        const int w  = (ww * 8 + c + SSZ) & 255;
        const int ch0 = tid >> 6;
        const long base = ((long)b * CDIM * HDIM + (long)h) * 256 + w;
        #pragma unroll
        for (int it = 0; it < 32; ++it) {
            int ch = ch0 + it * 4;
            out[base + (long)ch * (HDIM * 256)] = qk[l * PO_STRIDE + ch];
        }
    }
}

extern "C" void kernel_launch(void* const* d_in, const int* in_sizes, int n_in,
                              void* d_out, int out_size) {
    (void)in_sizes; (void)n_in; (void)out_size;
    const float* x     = (const float*)d_in[0];
    const float* wqkv  = (const float*)d_in[1];
    const float* wproj = (const float*)d_in[2];
    const float* bproj = (const float*)d_in[3];
    float* out = (float*)d_out;

    cudaFuncSetAttribute(swin_attn_kernel,
                         cudaFuncAttributeMaxDynamicSharedMemorySize, SMEM_BYTES);
    swin_attn_kernel<<<NWIN, 256, SMEM_BYTES>>>(x, wqkv, wproj, bproj, out);
}

// round 3
// speedup vs baseline: 1.4783x; 1.4783x over previous
#include <cuda_runtime.h>
#include <cuda_bf16.h>
#include <cstdint>

// ---------------- problem constants ----------------
#define HEADS 4
#define DHD   32
#define SCALE 0.1767766952966369f   // 32^-0.5

// ---------------- smem layout (bytes) ----------------
#define STRA  136                    // bf16 row stride of A/W tiles (272 B)
#define STRQ  132                    // fp32 row stride of Q/K/V/PO
#define SA_H  0
#define SA_L  17408
#define SW_H  34816
#define SW_L  52224
#define SQ    69632
#define QKV_SZ 33792                 // 64*132*4
#define SMEM_BYTES (SQ + 3 * QKV_SZ) // 171008

// ---------------- ptx helpers ----------------
__device__ __forceinline__ uint32_t smem_u32(const void* p) {
    uint32_t a;
    asm("{ .reg .u64 t; cvta.to.shared.u64 t, %1; cvt.u32.u64 %0, t; }" : "=r"(a) : "l"(p));
    return a;
}
__device__ __forceinline__ void ldsm4(uint32_t* r, uint32_t addr) {
    asm volatile("ldmatrix.sync.aligned.m8n8.x4.shared.b16 {%0,%1,%2,%3}, [%4];"
                 : "=r"(r[0]), "=r"(r[1]), "=r"(r[2]), "=r"(r[3]) : "r"(addr));
}
__device__ __forceinline__ void mma16816(float* c, const uint32_t* a,
                                         uint32_t b0, uint32_t b1) {
    asm volatile(
        "mma.sync.aligned.m16n8k16.row.col.f32.bf16.bf16.f32 "
        "{%0,%1,%2,%3}, {%4,%5,%6,%7}, {%8,%9}, {%0,%1,%2,%3};"
        : "+f"(c[0]), "+f"(c[1]), "+f"(c[2]), "+f"(c[3])
        : "r"(a[0]), "r"(a[1]), "r"(a[2]), "r"(a[3]), "r"(b0), "r"(b1));
}

// ---------------- packed f32x2 (FFMA2) helpers ----------------
__device__ __forceinline__ unsigned long long pk2(float x, float y) {
    unsigned long long r;
    asm("mov.b64 %0, {%1,%2};" : "=l"(r) : "f"(x), "f"(y));
    return r;
}
__device__ __forceinline__ void upk2(unsigned long long v, float& x, float& y) {
    asm("mov.b64 {%0,%1}, %2;" : "=f"(x), "=f"(y) : "l"(v));
}
__device__ __forceinline__ unsigned long long ffma2(unsigned long long a,
                                                    unsigned long long b,
                                                    unsigned long long c) {
    unsigned long long d;
    asm("fma.rn.f32x2 %0, %1, %2, %3;" : "=l"(d) : "l"(a), "l"(b), "l"(c));
    return d;
}

// ---------------- persistent transposed/split weights ----------------
__device__ __nv_bfloat16 g_wqkvT_h[384 * 128];   // [n][k] row-major
__device__ __nv_bfloat16 g_wqkvT_l[384 * 128];
__device__ __nv_bfloat16 g_wprojT_h[128 * 128];
__device__ __nv_bfloat16 g_wprojT_l[128 * 128];

__global__ void init_weights_kernel(const float* __restrict__ wqkv,
                                    const float* __restrict__ wproj) {
    int t = blockIdx.x * blockDim.x + threadIdx.x;   // 65536
    if (t < 49152) {
        int n = t >> 7, k = t & 127;
        float v = wqkv[k * 384 + n];
        __nv_bfloat16 h = __float2bfloat16(v);
        g_wqkvT_h[n * 128 + k] = h;
        g_wqkvT_l[n * 128 + k] = __float2bfloat16(v - __bfloat162float(h));
    } else {
        int r = t - 49152;
        int n = r >> 7, k = r & 127;
        float v = wproj[k * 128 + n];
        __nv_bfloat16 h = __float2bfloat16(v);
        g_wprojT_h[n * 128 + k] = h;
        g_wprojT_l[n * 128 + k] = __float2bfloat16(v - __bfloat162float(h));
    }
}

// ---------------- main kernel: 1 window per CTA ----------------
__global__ __launch_bounds__(256, 1)
void swin_mma_kernel(const float* __restrict__ x,
                     const float* __restrict__ bproj,
                     float* __restrict__ out) {
    extern __shared__ char smem[];
    const uint32_t sb = smem_u32(smem);
    const int tid  = threadIdx.x;
    const int wid  = tid >> 5;
    const int lane = tid & 31;

    const int bid = blockIdx.x;
    const int b   = bid >> 10;
    const int wh  = (bid >> 5) & 31;
    const int ww  = bid & 31;

    const int l    = tid & 63;
    const int rr   = l >> 3, cc8 = l & 7;
    const int cpar = tid >> 6;                 // 0..3
    const int gh   = (wh * 8 + rr + 4) & 255;
    const int gw   = (ww * 8 + cc8 + 4) & 255;
    const size_t gbase = (size_t)b * (128u * 65536u) + (size_t)gh * 256 + (size_t)gw;

    __nv_bfloat16* Ah = (__nv_bfloat16*)(smem + SA_H);
    __nv_bfloat16* Al = (__nv_bfloat16*)(smem + SA_L);

    // ---- Phase 1: gather + fp32 -> bf16 hi/lo split into A tile ----
    #pragma unroll 8
    for (int it = 0; it < 32; ++it) {
        int ch = cpar + it * 4;
        float v = x[gbase + (size_t)ch * 65536u];
        __nv_bfloat16 h = __float2bfloat16(v);
        Ah[l * STRA + ch] = h;
        Al[l * STRA + ch] = __float2bfloat16(v - __bfloat162float(h));
    }
    __syncthreads();

    // warp tiling: 4 (M) x 2 (N) warps; warp tile 16x32
    const int m0 = (wid >> 1) * 16;
    const int nb = (wid & 1) * 32;
    const int gid = lane >> 2, tig = lane & 3;

    // ldmatrix address components (byte offsets within a tile region)
    const uint32_t aOffBase =
        (uint32_t)((m0 + ((lane >> 3) & 1) * 8 + (lane & 7)) * 272 + ((lane >> 4) * 8) * 2);
    const uint32_t bRowOff = (uint32_t)((((lane >> 4) & 1) * 8 + (lane & 7)) * 272);
    const uint32_t bKOff   = (uint32_t)(((lane >> 3) & 1) * 8 * 2);

    // ---- Phase 2: QKV GEMM, 6 chunks of N=64, 3-pass bf16 split ----
    for (int ch = 0; ch < 6; ++ch) {
        {
            const uint4* srcH = (const uint4*)(g_wqkvT_h + (size_t)ch * 64 * 128);
            const uint4* srcL = (const uint4*)(g_wqkvT_l + (size_t)ch * 64 * 128);
            #pragma unroll
            for (int i = 0; i < 4; ++i) {
                int idx = tid + i * 256;                  // 0..1023
                int row = idx >> 4, col = idx & 15;
                *(uint4*)(smem + SW_H + row * 272 + col * 16) = srcH[idx];
                *(uint4*)(smem + SW_L + row * 272 + col * 16) = srcL[idx];
            }
        }
        __syncthreads();

        float acc[4][4];
        #pragma unroll
        for (int j = 0; j < 4; ++j)
            #pragma unroll
            for (int q = 0; q < 4; ++q) acc[j][q] = 0.f;

        #pragma unroll
        for (int kk = 0; kk < 8; ++kk) {
            const uint32_t ka = kk * 32;                  // k0*2 bytes
            uint32_t ah[4], al[4], bh[2][4], bl[2][4];
            ldsm4(ah, sb + SA_H + aOffBase + ka);
            ldsm4(al, sb + SA_L + aOffBase + ka);
            #pragma unroll
            for (int g = 0; g < 2; ++g) {
                uint32_t ro = (uint32_t)((nb + g * 16) * 272) + bRowOff + bKOff + ka;
                ldsm4(bh[g], sb + SW_H + ro);
                ldsm4(bl[g], sb + SW_L + ro);
            }
            #pragma unroll
            for (int j = 0; j < 4; ++j) {
                const int g = j >> 1, e = (j & 1) * 2;
                mma16816(acc[j], ah, bh[g][e], bh[g][e + 1]);
                mma16816(acc[j], ah, bl[g][e], bl[g][e + 1]);
                mma16816(acc[j], al, bh[g][e], bh[g][e + 1]);
            }
        }

        // store C tile to Q/K/V fp32
        {
            float* D = (float*)(smem + SQ + (ch >> 1) * QKV_SZ);
            const int colb = (ch & 1) * 64 + nb;
            #pragma unroll
            for (int j = 0; j < 4; ++j) {
                int ccol = colb + j * 8 + 2 * tig;
                *(float2*)&D[(m0 + gid) * STRQ + ccol]     = make_float2(acc[j][0], acc[j][1]);
                *(float2*)&D[(m0 + gid + 8) * STRQ + ccol] = make_float2(acc[j][2], acc[j][3]);
            }
        }
        __syncthreads();
    }

    // ---- Phase 3: attention (fp32 FFMA2, proven round-1 structure) ----
    {
        const float* Qs = (const float*)(smem + SQ);
        const float* Ks = (const float*)(smem + SQ + QKV_SZ);
        const float* Vs = (const float*)(smem + SQ + 2 * QKV_SZ);
        const int hh = tid >> 6;                  // head
        // q row, pre-scaled
        unsigned long long q2[16];
        const float* qrow = &Qs[l * STRQ + hh * DHD];
        #pragma unroll
        for (int d2 = 0; d2 < 16; ++d2) {
            unsigned long long v = *(const unsigned long long*)&qrow[2 * d2];
            float qx, qy; upk2(v, qx, qy);
            q2[d2] = pk2(qx * SCALE, qy * SCALE);
        }
        float s[64];
        #pragma unroll
        for (int m = 0; m < 64; ++m) {
            const float* kr = &Ks[m * STRQ + hh * DHD];
            unsigned long long a = 0ull;
            #pragma unroll
            for (int d2 = 0; d2 < 16; ++d2)
                a = ffma2(q2[d2], *(const unsigned long long*)&kr[2 * d2], a);
            float ax, ay; upk2(a, ax, ay);
            s[m] = ax + ay;
        }
        float mx = -1e30f;
        #pragma unroll
        for (int m = 0; m < 64; ++m) mx = fmaxf(mx, s[m]);
        float sum = 0.f;
        #pragma unroll
        for (int m = 0; m < 64; ++m) { float e = __expf(s[m] - mx); s[m] = e; sum += e; }
        const float inv = 1.0f / sum;
        unsigned long long o2[16];
        #pragma unroll
        for (int d2 = 0; d2 < 16; ++d2) o2[d2] = 0ull;
        #pragma unroll
        for (int m = 0; m < 64; ++m) {
            unsigned long long p2 = pk2(s[m], s[m]);
            const float* vr = &Vs[m * STRQ + hh * DHD];
            #pragma unroll
            for (int d2 = 0; d2 < 16; ++d2)
                o2[d2] = ffma2(p2, *(const unsigned long long*)&vr[2 * d2], o2[d2]);
        }
        __syncthreads();   // everyone done reading Q/K/V before A-tile overwrite? (A-tile is
                           // separate region; this sync orders AO writes vs GEMM2 reads below)
        #pragma unroll
        for (int d2 = 0; d2 < 16; ++d2) {
            float ox, oy; upk2(o2[d2], ox, oy);
            ox *= inv; oy *= inv;
            __nv_bfloat16 hx = __float2bfloat16(ox);
            __nv_bfloat16 hy = __float2bfloat16(oy);
            int e = l * STRA + hh * DHD + 2 * d2;
            Ah[e]     = hx;
            Ah[e + 1] = hy;
            Al[e]     = __float2bfloat16(ox - __bfloat162float(hx));
            Al[e + 1] = __float2bfloat16(oy - __bfloat162float(hy));
        }
    }
    __syncthreads();

    // ---- Phase 4: proj GEMM (2 chunks of N=64) + bias -> PO (= SQ region) ----
    for (int ch = 0; ch < 2; ++ch) {
        {
            const uint4* srcH = (const uint4*)(g_wprojT_h + (size_t)ch * 64 * 128);
            const uint4* srcL = (const uint4*)(g_wprojT_l + (size_t)ch * 64 * 128);
            #pragma unroll
            for (int i = 0; i < 4; ++i) {
                int idx = tid + i * 256;
                int row = idx >> 4, col = idx & 15;
                *(uint4*)(smem + SW_H + row * 272 + col * 16) = srcH[idx];
                *(uint4*)(smem + SW_L + row * 272 + col * 16) = srcL[idx];
            }
        }
        __syncthreads();

        float acc[4][4];
        #pragma unroll
        for (int j = 0; j < 4; ++j)
            #pragma unroll
            for (int q = 0; q < 4; ++q) acc[j][q] = 0.f;

        #pragma unroll
        for (int kk = 0; kk < 8; ++kk) {
            const uint32_t ka = kk * 32;
            uint32_t ah[4], al[4], bh[2][4], bl[2][4];
            ldsm4(ah, sb + SA_H + aOffBase + ka);
            ldsm4(al, sb + SA_L + aOffBase + ka);
            #pragma unroll
            for (int g = 0; g < 2; ++g) {
                uint32_t ro = (uint32_t)((nb + g * 16) * 272) + bRowOff + bKOff + ka;
                ldsm4(bh[g], sb + SW_H + ro);
                ldsm4(bl[g], sb + SW_L + ro);
            }
            #pragma unroll
            for (int j = 0; j < 4; ++j) {
                const int g = j >> 1, e = (j & 1) * 2;
                mma16816(acc[j], ah, bh[g][e], bh[g][e + 1]);
                mma16816(acc[j], ah, bl[g][e], bl[g][e + 1]);
                mma16816(acc[j], al, bh[g][e], bh[g][e + 1]);
            }
        }
        {
            float* PO = (float*)(smem + SQ);
            const int colb = ch * 64 + nb;
            #pragma unroll
            for (int j = 0; j < 4; ++j) {
                int ccol = colb + j * 8 + 2 * tig;
                float b0 = __ldg(&bproj[ccol]), b1 = __ldg(&bproj[ccol + 1]);
                *(float2*)&PO[(m0 + gid) * STRQ + ccol] =
                    make_float2(acc[j][0] + b0, acc[j][1] + b1);
                *(float2*)&PO[(m0 + gid + 8) * STRQ + ccol] =
                    make_float2(acc[j][2] + b0, acc[j][3] + b1);
            }
        }
        __syncthreads();
    }

    // ---- Phase 5: scatter ----
    {
        const float* PO = (const float*)(smem + SQ);
        #pragma unroll 8
        for (int it = 0; it < 32; ++it) {
            int ch = cpar + it * 4;
            out[gbase + (size_t)ch * 65536u] = PO[l * STRQ + ch];
        }
    }
}

extern "C" void kernel_launch(void* const* d_in, const int* in_sizes, int n_in,
                              void* d_out, int out_size) {
    (void)in_sizes; (void)n_in; (void)out_size;
    const float* x     = (const float*)d_in[0];
    const float* wqkv  = (const float*)d_in[1];
    const float* wproj = (const float*)d_in[2];
    const float* bproj = (const float*)d_in[3];
    float* out = (float*)d_out;

    init_weights_kernel<<<256, 256>>>(wqkv, wproj);

    cudaFuncSetAttribute(swin_mma_kernel,
                         cudaFuncAttributeMaxDynamicSharedMemorySize, SMEM_BYTES);
    swin_mma_kernel<<<8192, 256, SMEM_BYTES>>>(x, bproj, out);
}